// round 3
// baseline (speedup 1.0000x reference)
#include <cuda_runtime.h>

typedef unsigned long long ull;

#define BATCH 1024
#define TLEN  200
#define DDIM  128
#define HDIM  128
#define NXC   384                     // 256 gate cols + 128 cand cols
#define MROWS (BATCH * TLEN)          // 204800

// Scratch: x-projection [B*T, 384] (gate pre-act cols 0..255, cand pre-act cols 256..383)
__device__ float g_xproj[(size_t)MROWS * NXC];

// ---------- packed f32x2 helpers (Blackwell FFMA2 path) ----------
__device__ __forceinline__ ull dup2(float v) {
    ull r; asm("mov.b64 %0,{%1,%1};" : "=l"(r) : "f"(v)); return r;
}
__device__ __forceinline__ ull pack2(float x, float y) {
    ull r; asm("mov.b64 %0,{%1,%2};" : "=l"(r) : "f"(x), "f"(y)); return r;
}
__device__ __forceinline__ float2 unpack2(ull v) {
    float2 f; asm("mov.b64 {%0,%1},%2;" : "=f"(f.x), "=f"(f.y) : "l"(v)); return f;
}
__device__ __forceinline__ void ffma2(ull &d, ull a, ull b) {
    asm("fma.rn.f32x2 %0,%1,%2,%0;" : "+l"(d) : "l"(a), "l"(b));
}
__device__ __forceinline__ ull addf2(ull a, ull b) {
    ull r; asm("add.rn.f32x2 %0,%1,%2;" : "=l"(r) : "l"(a), "l"(b)); return r;
}
__device__ __forceinline__ float tanhap(float x) {
    float r; asm("tanh.approx.f32 %0,%1;" : "=f"(r) : "f"(x)); return r;
}
__device__ __forceinline__ float sigap(float x) {   // sigmoid(x) = 0.5 + 0.5*tanh(x/2)
    return fmaf(tanhap(0.5f * x), 0.5f, 0.5f);
}

// =====================================================================
// Phase 1: xproj[r, :] = x[r, :] @ Wx[128, 384] + bias   (r = b*T + t)
// One CTA = 128 rows x ALL 384 cols (3 col-chunks of 128), full K=128
// X tile resident in smem -> X read from DRAM exactly once. 512 threads.
// =====================================================================
__global__ void __launch_bounds__(512, 1) dien_xproj_kernel(
    const float* __restrict__ X, const int* __restrict__ seqlen,
    const float* __restrict__ Wg, const float* __restrict__ bg,
    const float* __restrict__ Wc, const float* __restrict__ bc)
{
    extern __shared__ float sm[];
    float* xsT = sm;                 // [128 k][132 rows] transposed, padded
    float* ws  = sm + 128 * 132;     // [128 k][128 cols]

    const int tid = threadIdx.x;
    const int r0  = blockIdx.x * 128;

    // --- seq_len skip: tile dead iff every row has t >= seq_len[b] ---
    __shared__ int anyv;
    if (tid == 0) anyv = 0;
    __syncthreads();
    if (tid < 128) {
        int r = r0 + tid;
        int b = r / TLEN, t = r - b * TLEN;
        if (t < seqlen[b]) anyv = 1;
    }
    __syncthreads();
    if (!anyv) return;

    // --- load x tile transposed: xsT[k][r] (once) ---
    const float4* X4 = (const float4*)(X + (size_t)r0 * DDIM);
    #pragma unroll
    for (int idx = tid; idx < 4096; idx += 512) {
        int k4 = idx >> 7;           // 0..31
        int r  = idx & 127;
        float4 v = X4[(size_t)r * 32 + k4];
        int kb = k4 * 4;
        xsT[(kb + 0) * 132 + r] = v.x;
        xsT[(kb + 1) * 132 + r] = v.y;
        xsT[(kb + 2) * 132 + r] = v.z;
        xsT[(kb + 3) * 132 + r] = v.w;
    }

    const int tx = tid & 15;   // col group: cols tx*8 .. tx*8+7
    const int ty = tid >> 4;   // row group: rows ty*4 .. ty*4+3 (0..31)

    for (int ct = 0; ct < 3; ct++) {
        // --- load W chunk: ws[k][c] for cols ct*128.. ---
        __syncthreads();   // previous chunk's ws reads done
        if (ct < 2) {
            const float4* W4 = (const float4*)Wg;     // row = 64 float4
            #pragma unroll
            for (int idx = tid; idx < 4096; idx += 512) {
                int k = idx >> 5, c4 = idx & 31;
                *(float4*)&ws[k * 128 + c4 * 4] = W4[k * 64 + ct * 32 + c4];
            }
        } else {
            const float4* W4 = (const float4*)Wc;     // row = 32 float4
            #pragma unroll
            for (int idx = tid; idx < 4096; idx += 512) {
                int k = idx >> 5, c4 = idx & 31;
                *(float4*)&ws[k * 128 + c4 * 4] = W4[k * 32 + c4];
            }
        }
        __syncthreads();

        // acc[row i][col pair p], init with bias
        ull acc[4][4];
        {
            const float* bias = (ct < 2) ? (bg + ct * 128 + tx * 8) : (bc + tx * 8);
            #pragma unroll
            for (int p = 0; p < 4; p++) {
                ull bp = pack2(bias[2 * p], bias[2 * p + 1]);
                #pragma unroll
                for (int i = 0; i < 4; i++) acc[i][p] = bp;
            }
        }

        #pragma unroll 4
        for (int k = 0; k < 128; k++) {
            float4 av = ((const float4*)(xsT + k * 132))[ty];
            const ulonglong2* bk = (const ulonglong2*)(ws + k * 128);
            ulonglong2 b01 = bk[tx * 2];
            ulonglong2 b23 = bk[tx * 2 + 1];
            ull A0 = dup2(av.x), A1 = dup2(av.y), A2 = dup2(av.z), A3 = dup2(av.w);
            ffma2(acc[0][0], A0, b01.x); ffma2(acc[0][1], A0, b01.y);
            ffma2(acc[0][2], A0, b23.x); ffma2(acc[0][3], A0, b23.y);
            ffma2(acc[1][0], A1, b01.x); ffma2(acc[1][1], A1, b01.y);
            ffma2(acc[1][2], A1, b23.x); ffma2(acc[1][3], A1, b23.y);
            ffma2(acc[2][0], A2, b01.x); ffma2(acc[2][1], A2, b01.y);
            ffma2(acc[2][2], A2, b23.x); ffma2(acc[2][3], A2, b23.y);
            ffma2(acc[3][0], A3, b01.x); ffma2(acc[3][1], A3, b01.y);
            ffma2(acc[3][2], A3, b23.x); ffma2(acc[3][3], A3, b23.y);
        }

        // --- store ---
        #pragma unroll
        for (int i = 0; i < 4; i++) {
            size_t r = (size_t)(r0 + ty * 4 + i);
            float2 p0 = unpack2(acc[i][0]);
            float2 p1 = unpack2(acc[i][1]);
            float2 p2 = unpack2(acc[i][2]);
            float2 p3 = unpack2(acc[i][3]);
            float* dst = &g_xproj[r * NXC + ct * 128 + tx * 8];
            ((float4*)dst)[0] = make_float4(p0.x, p0.y, p1.x, p1.y);
            ((float4*)dst)[1] = make_float4(p2.x, p2.y, p3.x, p3.y);
        }
    }
}

// =====================================================================
// Phase 2: recurrent scan. 128 CTAs x 1024 threads (32 warps/SM).
// Gate weights (32 floats/thread) register-resident. k-split 8.
// f32x2 lanes = adjacent batch-row pairs.
// =====================================================================
__global__ void __launch_bounds__(1024, 1) dien_gru_kernel(
    const float* __restrict__ Wg, const float* __restrict__ Wc,
    const int* __restrict__ seqlen, float* __restrict__ out)
{
    extern __shared__ char smraw[];
    float* whc = (float*)smraw;                 // [128 k][128 col] cand h-weights 64KB
    ull*   hp  = (ull*)(smraw + 65536);         // [4 pair][128 k] h          4KB
    ull*   rhp = hp + 512;                      // [4 pair][128 k] r*h        4KB
    ull*   red = rhp + 512;                     // reduction stage 8192 ull  64KB

    const int tid   = threadIdx.x;
    const int rows0 = blockIdx.x * 8;

    // ---- load cand weights into smem, zero h ----
    #pragma unroll
    for (int i = tid; i < 128 * 128; i += 1024) whc[i] = Wc[128 * 128 + i];
    if (tid < 512) hp[tid] = 0ull;

    // ---- mapping: col jc, k-split q (16 k's each) ----
    const int jc = tid & 127;
    const int q  = tid >> 7;            // 0..7
    const int k0 = q * 16;

    float wgr[16], wgu[16];             // register-resident gate weights
    #pragma unroll
    for (int i = 0; i < 16; i++) {
        wgr[i] = Wg[(size_t)(128 + k0 + i) * 256 + jc];
        wgu[i] = Wg[(size_t)(128 + k0 + i) * 256 + jc + 128];
    }

    // ---- epilogue mapping: threads q<4 handle pair p=q, column jc ----
    const bool epi = (q < 4);
    const int sq0 = epi ? seqlen[rows0 + 2 * q]     : 0;
    const int sq1 = epi ? seqlen[rows0 + 2 * q + 1] : 0;
    int maxseq = 0;
    #pragma unroll
    for (int i = 0; i < 8; i++) maxseq = max(maxseq, seqlen[rows0 + i]);
    __syncthreads();

    const float* xb0 = epi ? g_xproj + ((size_t)(rows0 + 2 * q)     * TLEN) * NXC : g_xproj;
    const float* xb1 = epi ? g_xproj + ((size_t)(rows0 + 2 * q + 1) * TLEN) * NXC : g_xproj;

    const ulonglong2* hpv = (const ulonglong2*)hp  + (k0 >> 1);
    const ulonglong2* rhv = (const ulonglong2*)rhp + (k0 >> 1);

    for (int t = 0; t < maxseq; t++) {
        // prefetch x-projections (epilogue threads only; consumed much later)
        float xr0, xr1, xu0, xu1, xc0, xc1;
        if (epi) {
            const float* x0 = xb0 + (size_t)t * NXC;
            const float* x1 = xb1 + (size_t)t * NXC;
            xr0 = x0[jc];       xr1 = x1[jc];
            xu0 = x0[jc + 128]; xu1 = x1[jc + 128];
            xc0 = x0[jc + 256]; xc1 = x1[jc + 256];
        }

        // ---- gate GEMV partials: 2 cols x 4 row-pairs, 16 k's from regs ----
        ull accr[4] = {0,0,0,0}, accu[4] = {0,0,0,0};
        #pragma unroll
        for (int i = 0; i < 8; i++) {
            ulonglong2 a0 = hpv[i];
            ulonglong2 a1 = hpv[64 + i];
            ulonglong2 a2 = hpv[128 + i];
            ulonglong2 a3 = hpv[192 + i];
            ull w0 = dup2(wgr[2*i]), w1 = dup2(wgr[2*i+1]);
            ull v0 = dup2(wgu[2*i]), v1 = dup2(wgu[2*i+1]);
            ffma2(accr[0], a0.x, w0); ffma2(accr[0], a0.y, w1);
            ffma2(accr[1], a1.x, w0); ffma2(accr[1], a1.y, w1);
            ffma2(accr[2], a2.x, w0); ffma2(accr[2], a2.y, w1);
            ffma2(accr[3], a3.x, w0); ffma2(accr[3], a3.y, w1);
            ffma2(accu[0], a0.x, v0); ffma2(accu[0], a0.y, v1);
            ffma2(accu[1], a1.x, v0); ffma2(accu[1], a1.y, v1);
            ffma2(accu[2], a2.x, v0); ffma2(accu[2], a2.y, v1);
            ffma2(accu[3], a3.x, v0); ffma2(accu[3], a3.y, v1);
        }
        // stage partials: r at red[(q*8+P)*128+jc], u at red[(q*8+4+P)*128+jc]
        {
            ull* st = red + (q * 8) * 128 + jc;
            #pragma unroll
            for (int P = 0; P < 4; P++) { st[P * 128] = accr[P]; st[(4 + P) * 128] = accu[P]; }
        }
        __syncthreads();

        // ---- gate epilogue (threads q<4): finish pair q at col jc ----
        float r0g, r1g, u0g, u1g; float2 Ho;
        if (epi) {
            const ull* rd = red + q * 128 + jc;       // q' stride 1024, u offset 512
            ull zr = rd[0], zu = rd[512];
            #pragma unroll
            for (int qq = 1; qq < 8; qq++) {
                zr = addf2(zr, rd[qq * 1024]);
                zu = addf2(zu, rd[qq * 1024 + 512]);
            }
            float2 Zr = unpack2(zr), Zu = unpack2(zu);
            r0g = sigap(Zr.x + xr0); r1g = sigap(Zr.y + xr1);
            u0g = sigap(Zu.x + xu0); u1g = sigap(Zu.y + xu1);
            Ho = unpack2(hp[q * 128 + jc]);
            rhp[q * 128 + jc] = pack2(r0g * Ho.x, r1g * Ho.y);
        }
        __syncthreads();

        // ---- cand GEMV partials: col jc, 16 k's, weights from smem ----
        ull acc2[4] = {0,0,0,0};
        #pragma unroll
        for (int i = 0; i < 8; i++) {
            ulonglong2 a0 = rhv[i];
            ulonglong2 a1 = rhv[64 + i];
            ulonglong2 a2 = rhv[128 + i];
            ulonglong2 a3 = rhv[192 + i];
            ull w0 = dup2(whc[(k0 + 2*i) * 128 + jc]);
            ull w1 = dup2(whc[(k0 + 2*i + 1) * 128 + jc]);
            ffma2(acc2[0], a0.x, w0); ffma2(acc2[0], a0.y, w1);
            ffma2(acc2[1], a1.x, w0); ffma2(acc2[1], a1.y, w1);
            ffma2(acc2[2], a2.x, w0); ffma2(acc2[2], a2.y, w1);
            ffma2(acc2[3], a3.x, w0); ffma2(acc2[3], a3.y, w1);
        }
        // stage: red[(q*4+P)*128 + jc]
        {
            ull* st = red + (q * 4) * 128 + jc;
            #pragma unroll
            for (int P = 0; P < 4; P++) st[P * 128] = acc2[P];
        }
        __syncthreads();

        // ---- cand epilogue + state update (threads q<4) ----
        if (epi) {
            const ull* rd = red + q * 128 + jc;       // q' stride 512
            ull zc = rd[0];
            #pragma unroll
            for (int qq = 1; qq < 8; qq++) zc = addf2(zc, rd[qq * 512]);
            float2 Zc = unpack2(zc);
            float c0 = tanhap(Zc.x + xc0);
            float c1 = tanhap(Zc.y + xc1);
            float hn0 = fmaf(u0g, Ho.x - c0, c0);   // u*h + (1-u)*c
            float hn1 = fmaf(u1g, Ho.y - c1, c1);
            bool v0 = t < sq0, v1 = t < sq1;
            hp[q * 128 + jc] = pack2(v0 ? hn0 : Ho.x, v1 ? hn1 : Ho.y);
            if (v0) out[((size_t)(rows0 + 2 * q)     * TLEN + t) * HDIM + jc] = hn0;
            if (v1) out[((size_t)(rows0 + 2 * q + 1) * TLEN + t) * HDIM + jc] = hn1;
        }
        __syncthreads();
    }
}

// =====================================================================
extern "C" void kernel_launch(void* const* d_in, const int* in_sizes, int n_in,
                              void* d_out, int out_size)
{
    const float* X   = (const float*)d_in[0];
    const int*   seq = (const int*)  d_in[1];
    const float* Wg  = (const float*)d_in[2];
    const float* bg  = (const float*)d_in[3];
    const float* Wc  = (const float*)d_in[4];
    const float* bc  = (const float*)d_in[5];
    float* out = (float*)d_out;
    (void)in_sizes; (void)n_in;

    const int SMEM1 = (128 * 132 + 128 * 128) * 4;                // 133120 B
    const int SMEM2 = 65536 + 4096 + 4096 + 65536;                // 139264 B
    cudaFuncSetAttribute(dien_xproj_kernel, cudaFuncAttributeMaxDynamicSharedMemorySize, SMEM1);
    cudaFuncSetAttribute(dien_gru_kernel,   cudaFuncAttributeMaxDynamicSharedMemorySize, SMEM2);

    // outputs are zero for t >= seq_len; zero everything, phase 2 fills valid steps
    cudaMemsetAsync(d_out, 0, (size_t)out_size * sizeof(float));

    dien_xproj_kernel<<<MROWS / 128, 512, SMEM1>>>(X, seq, Wg, bg, Wc, bc);
    dien_gru_kernel<<<BATCH / 8, 1024, SMEM2>>>(Wg, Wc, seq, out);
}

// round 4
// speedup vs baseline: 1.3822x; 1.3822x over previous
#include <cuda_runtime.h>

typedef unsigned long long ull;

#define BATCH 1024
#define TLEN  200
#define DDIM  128
#define HDIM  128
#define NXC   384                     // 256 gate cols + 128 cand cols
#define MROWS (BATCH * TLEN)          // 204800

// Scratch: x-projection [B*T, 384]
__device__ float g_xproj[(size_t)MROWS * NXC];

// ---------- packed f32x2 helpers (Blackwell FFMA2 path) ----------
__device__ __forceinline__ ull dup2(float v) {
    ull r; asm("mov.b64 %0,{%1,%1};" : "=l"(r) : "f"(v)); return r;
}
__device__ __forceinline__ ull pack2(float x, float y) {
    ull r; asm("mov.b64 %0,{%1,%2};" : "=l"(r) : "f"(x), "f"(y)); return r;
}
__device__ __forceinline__ float2 unpack2(ull v) {
    float2 f; asm("mov.b64 {%0,%1},%2;" : "=f"(f.x), "=f"(f.y) : "l"(v)); return f;
}
__device__ __forceinline__ void ffma2(ull &d, ull a, ull b) {
    asm("fma.rn.f32x2 %0,%1,%2,%0;" : "+l"(d) : "l"(a), "l"(b));
}
__device__ __forceinline__ ull addf2(ull a, ull b) {
    ull r; asm("add.rn.f32x2 %0,%1,%2;" : "=l"(r) : "l"(a), "l"(b)); return r;
}
__device__ __forceinline__ float tanhap(float x) {
    float r; asm("tanh.approx.f32 %0,%1;" : "=f"(r) : "f"(x)); return r;
}
__device__ __forceinline__ float sigap(float x) {   // sigmoid(x) = 0.5 + 0.5*tanh(x/2)
    return fmaf(tanhap(0.5f * x), 0.5f, 0.5f);
}
__device__ __forceinline__ ull shflb(ull v, int m) {
    unsigned lo, hi;
    asm("mov.b64 {%0,%1},%2;" : "=r"(lo), "=r"(hi) : "l"(v));
    lo = __shfl_xor_sync(0xffffffffu, lo, m);
    hi = __shfl_xor_sync(0xffffffffu, hi, m);
    ull r; asm("mov.b64 %0,{%1,%2};" : "=l"(r) : "r"(lo), "r"(hi)); return r;
}
// 2-level bfly halving reduction over the 4 k-groups (lane bits 3,4).
// Input: a0..a3 = partials for pairs P0..P3. Output: lane with q = laneid>>3
// holds the FULL (all-k) sum for pair P == q.
__device__ __forceinline__ ull reduce4(ull a0, ull a1, ull a2, ull a3,
                                       bool qb1, bool qb0) {
    ull t0 = qb1 ? a0 : a2;  ull r0 = shflb(t0, 16);
    ull t1 = qb1 ? a1 : a3;  ull r1 = shflb(t1, 16);
    ull b0 = qb1 ? addf2(a2, r0) : addf2(a0, r0);   // holds P = qb1?2:0 over {q,q^2}
    ull b1 = qb1 ? addf2(a3, r1) : addf2(a1, r1);   // holds P = qb1?3:1
    ull t  = qb0 ? b0 : b1;  ull r = shflb(t, 8);
    return qb0 ? addf2(b1, r) : addf2(b0, r);       // P == q, full k
}

// =====================================================================
// Phase 1 (R2 version): xproj = X @ Wx + bias. BM128 x BN128, K 2x64,
// 256 thr, 2 CTAs/SM. Dead tiles skipped via seq_len.
// =====================================================================
__global__ void __launch_bounds__(256, 2) dien_xproj_kernel(
    const float* __restrict__ X, const int* __restrict__ seqlen,
    const float* __restrict__ Wg, const float* __restrict__ bg,
    const float* __restrict__ Wc, const float* __restrict__ bc)
{
    extern __shared__ float sm[];
    float* xsT = sm;                 // [64 k][132 rows]
    float* ws  = sm + 64 * 132;      // [64 k][128 cols]

    const int tid = threadIdx.x;
    const int r0  = blockIdx.y * 128;
    const int ct  = blockIdx.x;

    __shared__ int anyv;
    if (tid == 0) anyv = 0;
    __syncthreads();
    if (tid < 128) {
        int r = r0 + tid;
        int b = r / TLEN, t = r - b * TLEN;
        if (t < seqlen[b]) anyv = 1;
    }
    __syncthreads();
    if (!anyv) return;

    const int tx = tid & 15;
    const int ty = tid >> 4;

    ull acc[8][4];
    {
        const float* bias = (ct < 2) ? (bg + ct * 128 + tx * 8) : (bc + tx * 8);
        #pragma unroll
        for (int p = 0; p < 4; p++) {
            ull bp = pack2(bias[2 * p], bias[2 * p + 1]);
            #pragma unroll
            for (int i = 0; i < 8; i++) acc[i][p] = bp;
        }
    }

    const float4* X4 = (const float4*)(X + (size_t)r0 * DDIM);

    for (int c = 0; c < 2; c++) {
        #pragma unroll
        for (int idx = tid; idx < 2048; idx += 256) {
            int k4 = idx >> 7;
            int r  = idx & 127;
            float4 v = X4[(size_t)r * 32 + c * 16 + k4];
            int kb = k4 * 4;
            xsT[(kb + 0) * 132 + r] = v.x;
            xsT[(kb + 1) * 132 + r] = v.y;
            xsT[(kb + 2) * 132 + r] = v.z;
            xsT[(kb + 3) * 132 + r] = v.w;
        }
        if (ct < 2) {
            const float4* W4 = (const float4*)Wg;
            #pragma unroll
            for (int idx = tid; idx < 2048; idx += 256) {
                int k = idx >> 5, c4 = idx & 31;
                *(float4*)&ws[k * 128 + c4 * 4] = W4[(c * 64 + k) * 64 + ct * 32 + c4];
            }
        } else {
            const float4* W4 = (const float4*)Wc;
            #pragma unroll
            for (int idx = tid; idx < 2048; idx += 256) {
                int k = idx >> 5, c4 = idx & 31;
                *(float4*)&ws[k * 128 + c4 * 4] = W4[(c * 64 + k) * 32 + c4];
            }
        }
        __syncthreads();

        const float4*     a4 = (const float4*)xsT;
        const ulonglong2* b2 = (const ulonglong2*)ws;

        #pragma unroll 4
        for (int k = 0; k < 64; k++) {
            float4 av0 = a4[k * 33 + ty * 2];
            float4 av1 = a4[k * 33 + ty * 2 + 1];
            ulonglong2 b01 = b2[k * 32 + tx * 2];
            ulonglong2 b23 = b2[k * 32 + tx * 2 + 1];
            ull A[8];
            A[0] = dup2(av0.x); A[1] = dup2(av0.y); A[2] = dup2(av0.z); A[3] = dup2(av0.w);
            A[4] = dup2(av1.x); A[5] = dup2(av1.y); A[6] = dup2(av1.z); A[7] = dup2(av1.w);
            #pragma unroll
            for (int i = 0; i < 8; i++) {
                ffma2(acc[i][0], A[i], b01.x);
                ffma2(acc[i][1], A[i], b01.y);
                ffma2(acc[i][2], A[i], b23.x);
                ffma2(acc[i][3], A[i], b23.y);
            }
        }
        __syncthreads();
    }

    #pragma unroll
    for (int i = 0; i < 8; i++) {
        size_t r = (size_t)(r0 + ty * 8 + i);
        float2 p0 = unpack2(acc[i][0]);
        float2 p1 = unpack2(acc[i][1]);
        float2 p2 = unpack2(acc[i][2]);
        float2 p3 = unpack2(acc[i][3]);
        float* dst = &g_xproj[r * NXC + ct * 128 + tx * 8];
        ((float4*)dst)[0] = make_float4(p0.x, p0.y, p1.x, p1.y);
        ((float4*)dst)[1] = make_float4(p2.x, p2.y, p3.x, p3.y);
    }
}

// =====================================================================
// Phase 2: warp-local k-split GRU. 128 CTAs x 512 thr, 8 rows each.
// lane = q*8 + jl : warp w owns cols jc = w*8+jl, k-group q (32 k's).
// Reductions via shfl.bfly (no smem staging). 2 barriers/step.
// h and r*h replicated 4x (bank-rotated) for conflict-free q-broadcasts.
// =====================================================================
#define REP_STRIDE 532          // ull per replica (4*130 + 12 pad -> +8 word banks/replica)
#define ROW_STRIDE 130          // ull per pair-row inside a replica

__global__ void __launch_bounds__(512, 1) dien_gru_kernel(
    const float* __restrict__ Wg, const float* __restrict__ Wc,
    const int* __restrict__ seqlen, float* __restrict__ out)
{
    extern __shared__ char smraw[];
    float* whc  = (float*)smraw;                    // [128 k][128 col], col-rotated, 64KB
    ull*   hp4  = (ull*)(smraw + 65536);            // 4 replicas x [4 P][130] h
    ull*   rhp4 = hp4 + 4 * REP_STRIDE;             // same for r*h

    const int tid   = threadIdx.x;
    const int rows0 = blockIdx.x * 8;
    const int lane  = tid & 31;
    const int w     = tid >> 5;          // warp 0..15
    const int jl    = lane & 7;
    const int q     = lane >> 3;         // k-group 0..3
    const int jc    = w * 8 + jl;        // column 0..127
    const int k0    = q * 32;
    const bool qb0  = (lane & 8)  != 0;
    const bool qb1  = (lane & 16) != 0;

    // ---- load cand weights with per-k-block column rotation ----
    for (int i = tid; i < 128 * 128; i += 512) {
        int k = i >> 7, jcc = i & 127;
        whc[k * 128 + ((jcc + (k >> 5) * 8) & 127)] = Wc[128 * 128 + i];
    }
    // ---- zero h replicas ----
    for (int i = tid; i < 8 * REP_STRIDE; i += 512) hp4[i] = 0ull;

    // ---- gate weights: 64 floats register-resident ----
    float wgr[32], wgu[32];
    #pragma unroll
    for (int i = 0; i < 32; i++) {
        wgr[i] = Wg[(size_t)(128 + k0 + i) * 256 + jc];
        wgu[i] = Wg[(size_t)(128 + k0 + i) * 256 + jc + 128];
    }

    const int sq0 = seqlen[rows0 + 2 * q];
    const int sq1 = seqlen[rows0 + 2 * q + 1];
    int maxseq = 0;
    #pragma unroll
    for (int i = 0; i < 8; i++) maxseq = max(maxseq, seqlen[rows0 + i]);
    __syncthreads();

    const float* x0b = g_xproj + (size_t)(rows0 + 2 * q)     * TLEN * NXC;
    const float* x1b = g_xproj + (size_t)(rows0 + 2 * q + 1) * TLEN * NXC;

    // ull2 views of this lane's replica, pre-offset by k-window
    const ulonglong2* h2 = (const ulonglong2*)(hp4  + q * REP_STRIDE) + (k0 >> 1);
    const ulonglong2* r2 = (const ulonglong2*)(rhp4 + q * REP_STRIDE) + (k0 >> 1);
    const int rc = (jc + q * 8) & 127;   // rotated whc column for this k-group
    const float* wcp = whc + k0 * 128 + rc;

    for (int t = 0; t < maxseq; t++) {
        // prefetch x-projections (consumed after the GEMV loops)
        const float* x0 = x0b + (size_t)t * NXC;
        const float* x1 = x1b + (size_t)t * NXC;
        float xr0 = x0[jc],       xr1 = x1[jc];
        float xu0 = x0[jc + 128], xu1 = x1[jc + 128];
        float xc0 = x0[jc + 256], xc1 = x1[jc + 256];

        // ---- gate GEMV partials: col jc (r,u), 4 pairs, 32 k's from regs ----
        ull ar0=0, ar1=0, ar2=0, ar3=0, au0=0, au1=0, au2=0, au3=0;
        #pragma unroll
        for (int i = 0; i < 16; i++) {
            ulonglong2 a0 = h2[i];
            ulonglong2 a1 = h2[65  + i];
            ulonglong2 a2 = h2[130 + i];
            ulonglong2 a3 = h2[195 + i];
            ull w0 = dup2(wgr[2*i]), w1 = dup2(wgr[2*i+1]);
            ull v0 = dup2(wgu[2*i]), v1 = dup2(wgu[2*i+1]);
            ffma2(ar0, a0.x, w0); ffma2(ar0, a0.y, w1);
            ffma2(ar1, a1.x, w0); ffma2(ar1, a1.y, w1);
            ffma2(ar2, a2.x, w0); ffma2(ar2, a2.y, w1);
            ffma2(ar3, a3.x, w0); ffma2(ar3, a3.y, w1);
            ffma2(au0, a0.x, v0); ffma2(au0, a0.y, v1);
            ffma2(au1, a1.x, v0); ffma2(au1, a1.y, v1);
            ffma2(au2, a2.x, v0); ffma2(au2, a2.y, v1);
            ffma2(au3, a3.x, v0); ffma2(au3, a3.y, v1);
        }
        // warp-local reduction over k-groups: lane ends with pair P == q
        ull zr = reduce4(ar0, ar1, ar2, ar3, qb1, qb0);
        ull zu = reduce4(au0, au1, au2, au3, qb1, qb0);

        float2 Zr = unpack2(zr), Zu = unpack2(zu);
        float r0g = sigap(Zr.x + xr0), r1g = sigap(Zr.y + xr1);
        float u0g = sigap(Zu.x + xu0), u1g = sigap(Zu.y + xu1);
        float2 Ho = unpack2(hp4[q * ROW_STRIDE + jc]);   // replica 0, P = q
        ull rh = pack2(r0g * Ho.x, r1g * Ho.y);
        #pragma unroll
        for (int rr = 0; rr < 4; rr++) rhp4[rr * REP_STRIDE + q * ROW_STRIDE + jc] = rh;
        __syncthreads();

        // ---- cand GEMV partials: col jc, 4 pairs, 32 k's, weights from smem ----
        ull ac0=0, ac1=0, ac2=0, ac3=0;
        #pragma unroll
        for (int i = 0; i < 16; i++) {
            ulonglong2 a0 = r2[i];
            ulonglong2 a1 = r2[65  + i];
            ulonglong2 a2 = r2[130 + i];
            ulonglong2 a3 = r2[195 + i];
            ull w0 = dup2(wcp[(2*i)     * 128]);
            ull w1 = dup2(wcp[(2*i + 1) * 128]);
            ffma2(ac0, a0.x, w0); ffma2(ac0, a0.y, w1);
            ffma2(ac1, a1.x, w0); ffma2(ac1, a1.y, w1);
            ffma2(ac2, a2.x, w0); ffma2(ac2, a2.y, w1);
            ffma2(ac3, a3.x, w0); ffma2(ac3, a3.y, w1);
        }
        ull zc = reduce4(ac0, ac1, ac2, ac3, qb1, qb0);

        // ---- state update: this lane owns (pair q, col jc) ----
        {
            float2 Zc = unpack2(zc);
            float c0 = tanhap(Zc.x + xc0);
            float c1 = tanhap(Zc.y + xc1);
            float hn0 = fmaf(u0g, Ho.x - c0, c0);   // u*h + (1-u)*c
            float hn1 = fmaf(u1g, Ho.y - c1, c1);
            bool v0 = t < sq0, v1 = t < sq1;
            ull hnew = pack2(v0 ? hn0 : Ho.x, v1 ? hn1 : Ho.y);
            #pragma unroll
            for (int rr = 0; rr < 4; rr++) hp4[rr * REP_STRIDE + q * ROW_STRIDE + jc] = hnew;
            if (v0) out[((size_t)(rows0 + 2 * q)     * TLEN + t) * HDIM + jc] = hn0;
            if (v1) out[((size_t)(rows0 + 2 * q + 1) * TLEN + t) * HDIM + jc] = hn1;
        }
        __syncthreads();
    }
}

// =====================================================================
extern "C" void kernel_launch(void* const* d_in, const int* in_sizes, int n_in,
                              void* d_out, int out_size)
{
    const float* X   = (const float*)d_in[0];
    const int*   seq = (const int*)  d_in[1];
    const float* Wg  = (const float*)d_in[2];
    const float* bg  = (const float*)d_in[3];
    const float* Wc  = (const float*)d_in[4];
    const float* bc  = (const float*)d_in[5];
    float* out = (float*)d_out;
    (void)in_sizes; (void)n_in;

    const int SMEM1 = (64 * 132 + 64 * 128) * 4;                  // 66560 B
    const int SMEM2 = 65536 + 8 * REP_STRIDE * 8;                 // 65536 + 34048 B
    cudaFuncSetAttribute(dien_xproj_kernel, cudaFuncAttributeMaxDynamicSharedMemorySize, SMEM1);
    cudaFuncSetAttribute(dien_gru_kernel,   cudaFuncAttributeMaxDynamicSharedMemorySize, SMEM2);

    cudaMemsetAsync(d_out, 0, (size_t)out_size * sizeof(float));

    dim3 g1(3, MROWS / 128);
    dien_xproj_kernel<<<g1, 256, SMEM1>>>(X, seq, Wg, bg, Wc, bc);
    dien_gru_kernel<<<BATCH / 8, 512, SMEM2>>>(Wg, Wc, seq, out);
}